// round 9
// baseline (speedup 1.0000x reference)
#include <cuda_runtime.h>
#include <cuda_bf16.h>
#include <math.h>
#include <stdint.h>

#define BB 64
#define TT 1024
#define FF 128
#define UU 256

typedef unsigned long long ull;

// ---------------------------------------------------------------------------
// Packed f32x2 helpers (sm_100+): two independent fp32 FMAs per instruction,
// exact fp32 arithmetic.
// ---------------------------------------------------------------------------
__device__ __forceinline__ void ffma2(ull &d, ull a, ull b) {
    asm("fma.rn.f32x2 %0, %1, %2, %0;" : "+l"(d) : "l"(a), "l"(b));
}
__device__ __forceinline__ ull packf2(float lo, float hi) {
    ull r;
    asm("mov.b64 %0, {%1, %2};" : "=l"(r) : "f"(lo), "f"(hi));
    return r;
}
__device__ __forceinline__ float f2lo(ull v) { return __uint_as_float((unsigned)v); }
__device__ __forceinline__ float f2hi(ull v) { return __uint_as_float((unsigned)(v >> 32)); }

// Fast tanh via MUFU.EX2 + MUFU.RCP (rel err ~1e-6 on this recurrence's range).
__device__ __forceinline__ float tanh_fast(float y) {
    float e = __expf(2.0f * y);
    return 1.0f - __fdividef(2.0f, e + 1.0f);
}

// ---------------------------------------------------------------------------
// Kernel 1: projection  h[t,b,u] = sum_f inputs[b,t,f] * R[f,u]
// Written into d_out ([T,B,U]); the recurrence kernel overwrites in place.
// Grid (2, B) = 128 CTAs (one wave), 256 threads. Each CTA: 512 t-rows in
// 16 chunks of 32, R filled into smem ONCE (vs every-CTA in R7 -> ~250us).
// Next chunk's inputs are prefetched into registers before the barrier.
// ---------------------------------------------------------------------------
#define PROJ_SMEM (128 * 1024 + 32 * 128 * 4)
#define ROWS_PER_CTA 512
#define CHUNKS (ROWS_PER_CTA / 32)

__global__ __launch_bounds__(256, 1)
void proj_kernel(const float* __restrict__ inp, const float* __restrict__ R,
                 float* __restrict__ out)
{
    extern __shared__ ull smem_p[];
    ull*   Rs  = smem_p;                    // 16384 ull: Rs[p*256+u] = (R[2p][u], R[2p+1][u])
    float* xin = (float*)(smem_p + 16384);  // 32 rows x 128 floats

    const int tid = threadIdx.x;
    const int b   = blockIdx.y;
    const int tb  = blockIdx.x * ROWS_PER_CTA;

    // Fill Rs once (coalesced over u).
    #pragma unroll 1
    for (int i = 0; i < 64; ++i) {
        Rs[i * 256 + tid] = packf2(R[(2 * i) * UU + tid], R[(2 * i + 1) * UU + tid]);
    }

    const float4* src = (const float4*)(inp + (size_t)b * TT * FF + (size_t)tb * FF);
    // Prefetch chunk 0 into registers.
    float4 pf[4];
    #pragma unroll
    for (int i = 0; i < 4; ++i) pf[i] = src[tid + i * 256];

    const int uu = tid & 63;
    const int rg = tid >> 6;
    const int u0 = uu * 4;
    const ull* xr = (const ull*)xin;

    #pragma unroll 1
    for (int ch = 0; ch < CHUNKS; ++ch) {
        // Store prefetched chunk to smem, then prefetch the next one.
        float4* dst = (float4*)xin;
        #pragma unroll
        for (int i = 0; i < 4; ++i) dst[tid + i * 256] = pf[i];
        __syncthreads();

        int chn = (ch + 1 < CHUNKS) ? ch + 1 : ch;
        #pragma unroll
        for (int i = 0; i < 4; ++i) pf[i] = src[chn * 1024 + tid + i * 256];

        ull acc[32];
        #pragma unroll
        for (int i = 0; i < 32; ++i) acc[i] = 0ull;

        #pragma unroll 4
        for (int p = 0; p < 64; ++p) {
            ull w0 = Rs[p * 256 + u0 + 0];
            ull w1 = Rs[p * 256 + u0 + 1];
            ull w2 = Rs[p * 256 + u0 + 2];
            ull w3 = Rs[p * 256 + u0 + 3];
            #pragma unroll
            for (int ri = 0; ri < 8; ++ri) {
                ull xv = xr[(rg * 8 + ri) * 64 + p];
                ffma2(acc[ri * 4 + 0], xv, w0);
                ffma2(acc[ri * 4 + 1], xv, w1);
                ffma2(acc[ri * 4 + 2], xv, w2);
                ffma2(acc[ri * 4 + 3], xv, w3);
            }
        }

        #pragma unroll
        for (int ri = 0; ri < 8; ++ri) {
            int t = tb + ch * 32 + rg * 8 + ri;
            float4 v;
            v.x = f2lo(acc[ri * 4 + 0]) + f2hi(acc[ri * 4 + 0]);
            v.y = f2lo(acc[ri * 4 + 1]) + f2hi(acc[ri * 4 + 1]);
            v.z = f2lo(acc[ri * 4 + 2]) + f2hi(acc[ri * 4 + 2]);
            v.w = f2lo(acc[ri * 4 + 3]) + f2hi(acc[ri * 4 + 3]);
            *(float4*)(out + (size_t)t * (BB * UU) + (size_t)b * UU + u0) = v;
        }
        __syncthreads();   // protect xin before next chunk's store
    }
}

// ---------------------------------------------------------------------------
// Kernel 2: recurrence. One CTA per batch element (64 CTAs x 1024 threads).
//   x_t = tanh(h[t] + x_{t-1} @ W + bias)
// Thread (ug = tid&63, kq = tid>>6): u-cols [4ug..4ug+4), k in [16kq..16kq+16)
// = 8 k-pairs, ALL register-resident: 32 f32x2 W regs/thread (256 KB/CTA =
// the whole RF at 64 regs/thread, no smem W -> no 64KB/step crossbar term).
// kq is warp-uniform -> state LDS.128 are broadcasts. 16-way reduction via
// partial[kq][u] (STS.128 conflict-free) -> bar -> 256 threads finalize
// (16 conflict-free LDS.32, tree add, fast tanh) -> state + output -> bar.
// h[t] read from d_out (written by proj), overwritten in place by x_t.
// ---------------------------------------------------------------------------
__global__ __launch_bounds__(1024, 1)
void rec_kernel(const float* __restrict__ W, const float* __restrict__ bias,
                const float* __restrict__ x0, float* __restrict__ out)
{
    __shared__ float sxf[256];
    __shared__ float partial[16 * 256];   // 16 KB

    const int tid = threadIdx.x;
    const int b   = blockIdx.x;
    const int ug  = tid & 63;
    const int kq  = tid >> 6;            // 0..15, warp-uniform
    const int u0  = ug * 4;
    const int k0  = kq * 16;

    // --- W: 8 k-pairs x 4 u columns, all in registers ---
    ull wreg[4][8];
    #pragma unroll
    for (int p = 0; p < 8; ++p) {
        float4 va = *(const float4*)(W + (size_t)(k0 + 2 * p)     * UU + u0);
        float4 vb = *(const float4*)(W + (size_t)(k0 + 2 * p + 1) * UU + u0);
        wreg[0][p] = packf2(va.x, vb.x);
        wreg[1][p] = packf2(va.y, vb.y);
        wreg[2][p] = packf2(va.z, vb.z);
        wreg[3][p] = packf2(va.w, vb.w);
    }

    float breg = 0.f;
    if (tid < 256) {
        breg = bias[tid];
        sxf[tid] = x0[tid];
    }
    __syncthreads();

    float* outp = out + (size_t)b * UU + tid;                 // deref only tid<256
    const ulonglong2* sx2 = (const ulonglong2*)sxf + kq * 4;  // this kq's 8 pairs

    #pragma unroll 1
    for (int t = 0; t < TT; ++t) {
        // Prefetch h[t,b,u]; latency hides under the FMA loop.
        float hreg = 0.f;
        if (tid < 256) hreg = outp[(size_t)t * (BB * UU)];

        ull a0 = 0, a1 = 0, a2 = 0, a3 = 0;
        #pragma unroll
        for (int i = 0; i < 4; ++i) {
            ulonglong2 sp = sx2[i];                           // LDS.128 broadcast
            ffma2(a0, sp.x, wreg[0][2 * i]);     ffma2(a1, sp.x, wreg[1][2 * i]);
            ffma2(a2, sp.x, wreg[2][2 * i]);     ffma2(a3, sp.x, wreg[3][2 * i]);
            ffma2(a0, sp.y, wreg[0][2 * i + 1]); ffma2(a1, sp.y, wreg[1][2 * i + 1]);
            ffma2(a2, sp.y, wreg[2][2 * i + 1]); ffma2(a3, sp.y, wreg[3][2 * i + 1]);
        }

        float4 ps;
        ps.x = f2lo(a0) + f2hi(a0);
        ps.y = f2lo(a1) + f2hi(a1);
        ps.z = f2lo(a2) + f2hi(a2);
        ps.w = f2lo(a3) + f2hi(a3);
        *(float4*)(partial + kq * 256 + u0) = ps;             // STS.128 conflict-free
        __syncthreads();

        if (tid < 256) {
            float s0 = partial[            tid] + partial[ 1 * 256 + tid];
            float s1 = partial[ 2 * 256 + tid] + partial[ 3 * 256 + tid];
            float s2 = partial[ 4 * 256 + tid] + partial[ 5 * 256 + tid];
            float s3 = partial[ 6 * 256 + tid] + partial[ 7 * 256 + tid];
            float s4 = partial[ 8 * 256 + tid] + partial[ 9 * 256 + tid];
            float s5 = partial[10 * 256 + tid] + partial[11 * 256 + tid];
            float s6 = partial[12 * 256 + tid] + partial[13 * 256 + tid];
            float s7 = partial[14 * 256 + tid] + partial[15 * 256 + tid];
            float y  = (((s0 + s1) + (s2 + s3)) + ((s4 + s5) + (s6 + s7)))
                     + (hreg + breg);
            float x  = tanh_fast(y);
            sxf[tid] = x;                                     // new state
            outp[(size_t)t * (BB * UU)] = x;                  // overwrite h[t]
        }
        __syncthreads();
    }
}

// ---------------------------------------------------------------------------
// Launch. Inputs: inputs[B,T,F], R[F,U], W[U,U], bias[U], x0[U].
// Output: float32 states[T,B,U].
// ---------------------------------------------------------------------------
extern "C" void kernel_launch(void* const* d_in, const int* in_sizes, int n_in,
                              void* d_out, int out_size) {
    const float* inp  = (const float*)d_in[0];
    const float* R    = (const float*)d_in[1];
    const float* W    = (const float*)d_in[2];
    const float* bias = (const float*)d_in[3];
    const float* x0   = (const float*)d_in[4];
    float* out = (float*)d_out;

    cudaFuncSetAttribute(proj_kernel, cudaFuncAttributeMaxDynamicSharedMemorySize, PROJ_SMEM);

    proj_kernel<<<dim3(TT / ROWS_PER_CTA, BB), 256, PROJ_SMEM>>>(inp, R, out);
    rec_kernel<<<BB, 1024>>>(W, bias, x0, out);
}

// round 10
// speedup vs baseline: 2.2471x; 2.2471x over previous
#include <cuda_runtime.h>
#include <cuda_bf16.h>
#include <math.h>
#include <stdint.h>

#define BB 64
#define TT 1024
#define FF 128
#define UU 256

typedef unsigned long long ull;

// ---------------------------------------------------------------------------
// Packed f32x2 helpers (sm_100+): two independent fp32 FMAs per instruction,
// exact fp32 arithmetic.
// ---------------------------------------------------------------------------
__device__ __forceinline__ void ffma2(ull &d, ull a, ull b) {
    asm("fma.rn.f32x2 %0, %1, %2, %0;" : "+l"(d) : "l"(a), "l"(b));
}
__device__ __forceinline__ ull packf2(float lo, float hi) {
    ull r;
    asm("mov.b64 %0, {%1, %2};" : "=l"(r) : "f"(lo), "f"(hi));
    return r;
}
__device__ __forceinline__ float f2lo(ull v) { return __uint_as_float((unsigned)v); }
__device__ __forceinline__ float f2hi(ull v) { return __uint_as_float((unsigned)(v >> 32)); }

// Fast tanh via MUFU.EX2 + MUFU.RCP (rel err ~1e-6 on this recurrence's range).
__device__ __forceinline__ float tanh_fast(float y) {
    float e = __expf(2.0f * y);
    return 1.0f - __fdividef(2.0f, e + 1.0f);
}

// ---------------------------------------------------------------------------
// Kernel 1: projection  h[t,b,u] = sum_f inputs[b,t,f] * R[f,u]
// Written into d_out ([T,B,U]); the recurrence kernel overwrites in place.
// Grid (2, B) = 128 CTAs (one wave), 256 threads. Each CTA: 512 t-rows in
// 16 chunks of 32; R filled into smem ONCE per CTA (16x amortized vs R7).
// Next chunk's inputs prefetched into registers before the barrier.
// ---------------------------------------------------------------------------
#define PROJ_SMEM (128 * 1024 + 32 * 128 * 4)
#define ROWS_PER_CTA 512
#define CHUNKS (ROWS_PER_CTA / 32)

__global__ __launch_bounds__(256, 1)
void proj_kernel(const float* __restrict__ inp, const float* __restrict__ R,
                 float* __restrict__ out)
{
    extern __shared__ ull smem_p[];
    ull*   Rs  = smem_p;                    // 16384 ull: Rs[p*256+u] = (R[2p][u], R[2p+1][u])
    float* xin = (float*)(smem_p + 16384);  // 32 rows x 128 floats

    const int tid = threadIdx.x;
    const int b   = blockIdx.y;
    const int tb  = blockIdx.x * ROWS_PER_CTA;

    // Fill Rs once (coalesced over u).
    #pragma unroll 1
    for (int i = 0; i < 64; ++i) {
        Rs[i * 256 + tid] = packf2(R[(2 * i) * UU + tid], R[(2 * i + 1) * UU + tid]);
    }

    const float4* src = (const float4*)(inp + (size_t)b * TT * FF + (size_t)tb * FF);
    float4 pf[4];
    #pragma unroll
    for (int i = 0; i < 4; ++i) pf[i] = src[tid + i * 256];

    const int uu = tid & 63;
    const int rg = tid >> 6;
    const int u0 = uu * 4;
    const ull* xr = (const ull*)xin;

    #pragma unroll 1
    for (int ch = 0; ch < CHUNKS; ++ch) {
        float4* dst = (float4*)xin;
        #pragma unroll
        for (int i = 0; i < 4; ++i) dst[tid + i * 256] = pf[i];
        __syncthreads();

        int chn = (ch + 1 < CHUNKS) ? ch + 1 : ch;
        #pragma unroll
        for (int i = 0; i < 4; ++i) pf[i] = src[chn * 1024 + tid + i * 256];

        ull acc[32];
        #pragma unroll
        for (int i = 0; i < 32; ++i) acc[i] = 0ull;

        #pragma unroll 4
        for (int p = 0; p < 64; ++p) {
            ull w0 = Rs[p * 256 + u0 + 0];
            ull w1 = Rs[p * 256 + u0 + 1];
            ull w2 = Rs[p * 256 + u0 + 2];
            ull w3 = Rs[p * 256 + u0 + 3];
            #pragma unroll
            for (int ri = 0; ri < 8; ++ri) {
                ull xv = xr[(rg * 8 + ri) * 64 + p];
                ffma2(acc[ri * 4 + 0], xv, w0);
                ffma2(acc[ri * 4 + 1], xv, w1);
                ffma2(acc[ri * 4 + 2], xv, w2);
                ffma2(acc[ri * 4 + 3], xv, w3);
            }
        }

        #pragma unroll
        for (int ri = 0; ri < 8; ++ri) {
            int t = tb + ch * 32 + rg * 8 + ri;
            float4 v;
            v.x = f2lo(acc[ri * 4 + 0]) + f2hi(acc[ri * 4 + 0]);
            v.y = f2lo(acc[ri * 4 + 1]) + f2hi(acc[ri * 4 + 1]);
            v.z = f2lo(acc[ri * 4 + 2]) + f2hi(acc[ri * 4 + 2]);
            v.w = f2lo(acc[ri * 4 + 3]) + f2hi(acc[ri * 4 + 3]);
            *(float4*)(out + (size_t)t * (BB * UU) + (size_t)b * UU + u0) = v;
        }
        __syncthreads();   // protect xin before next chunk's store
    }
}

// ---------------------------------------------------------------------------
// Kernel 2: recurrence — R7 configuration (measured 683us, regs=128, NO
// spills; the 1024-thread all-register variant spills W and is 2.4x slower).
// One CTA per batch element (64 CTAs x 512 threads).
//   x_t = tanh(h[t] + x_{t-1} @ W + bias)
// Thread (ug = tid&63, kq = tid>>6) covers u in [4ug, 4ug+4),
// k in [32kq, 32kq+32) = 16 k-pairs:
//   pairs 0..11  -> registers (96 regs/thread, 192 KB/CTA)
//   pairs 12..15 -> smem as ulonglong2[8][512], conflict-free LDS.128
// Per step: FMA loop -> partial STS.128 -> bar -> 256-thread tree reduce +
// fast tanh -> state + output -> bar.
// ---------------------------------------------------------------------------
#define REC_SMEM (64 * 1024 + 256 * 4 + 8 * 256 * 4)

__global__ __launch_bounds__(512, 1)
void rec_kernel(const float* __restrict__ W, const float* __restrict__ bias,
                const float* __restrict__ x0, float* __restrict__ out)
{
    extern __shared__ ull smem_r[];
    ulonglong2* Wsm2    = (ulonglong2*)smem_r;         // 8 slots * 512 ull2 = 64 KB
    float*      sxf     = (float*)(smem_r + 8192);     // 256 floats (state)
    float*      partial = sxf + 256;                   // 8 * 256 floats

    const int tid = threadIdx.x;
    const int b   = blockIdx.x;
    const int kq  = tid >> 6;        // 0..7
    const int u0  = (tid & 63) * 4;
    const int k0  = kq * 32;

    // --- Load W partition ---
    ull wreg[4][12];
    #pragma unroll
    for (int p = 0; p < 16; ++p) {
        float4 va = *(const float4*)(W + (size_t)(k0 + 2 * p)     * UU + u0);
        float4 vb = *(const float4*)(W + (size_t)(k0 + 2 * p + 1) * UU + u0);
        ull w0 = packf2(va.x, vb.x);
        ull w1 = packf2(va.y, vb.y);
        ull w2 = packf2(va.z, vb.z);
        ull w3 = packf2(va.w, vb.w);
        if (p < 12) {
            wreg[0][p] = w0; wreg[1][p] = w1; wreg[2][p] = w2; wreg[3][p] = w3;
        } else {
            int q = p - 12;
            Wsm2[(q * 2 + 0) * 512 + tid] = make_ulonglong2(w0, w1);
            Wsm2[(q * 2 + 1) * 512 + tid] = make_ulonglong2(w2, w3);
        }
    }

    float breg = 0.f;
    if (tid < 256) {
        breg = bias[tid];
        sxf[tid] = x0[tid];
    }
    __syncthreads();

    float* outp = out + (size_t)b * UU + tid;                 // deref only tid<256
    const ulonglong2* sx2 = (const ulonglong2*)sxf + kq * 8;  // this kq's 16 pairs

    #pragma unroll 1
    for (int t = 0; t < TT; ++t) {
        // Prefetch h[t,b,u]; DRAM/L2 latency hides under the FMA loop.
        float hreg = 0.f;
        if (tid < 256) hreg = outp[(size_t)t * (BB * UU)];

        ull acc0 = 0, acc1 = 0, acc2 = 0, acc3 = 0;

        // k-pairs 0..11: register-resident W
        #pragma unroll
        for (int i = 0; i < 6; ++i) {
            ulonglong2 xp = sx2[i];                           // LDS.128 broadcast
            ffma2(acc0, xp.x, wreg[0][2 * i]);
            ffma2(acc1, xp.x, wreg[1][2 * i]);
            ffma2(acc2, xp.x, wreg[2][2 * i]);
            ffma2(acc3, xp.x, wreg[3][2 * i]);
            ffma2(acc0, xp.y, wreg[0][2 * i + 1]);
            ffma2(acc1, xp.y, wreg[1][2 * i + 1]);
            ffma2(acc2, xp.y, wreg[2][2 * i + 1]);
            ffma2(acc3, xp.y, wreg[3][2 * i + 1]);
        }
        // k-pairs 12..15: smem-resident W, conflict-free LDS.128
        #pragma unroll
        for (int i = 0; i < 2; ++i) {
            ulonglong2 xp = sx2[6 + i];
            {
                ulonglong2 wa0 = Wsm2[(i * 4 + 0) * 512 + tid];
                ulonglong2 wa1 = Wsm2[(i * 4 + 1) * 512 + tid];
                ffma2(acc0, xp.x, wa0.x);
                ffma2(acc1, xp.x, wa0.y);
                ffma2(acc2, xp.x, wa1.x);
                ffma2(acc3, xp.x, wa1.y);
            }
            {
                ulonglong2 wb0 = Wsm2[(i * 4 + 2) * 512 + tid];
                ulonglong2 wb1 = Wsm2[(i * 4 + 3) * 512 + tid];
                ffma2(acc0, xp.y, wb0.x);
                ffma2(acc1, xp.y, wb0.y);
                ffma2(acc2, xp.y, wb1.x);
                ffma2(acc3, xp.y, wb1.y);
            }
        }

        float4 ps;
        ps.x = f2lo(acc0) + f2hi(acc0);
        ps.y = f2lo(acc1) + f2hi(acc1);
        ps.z = f2lo(acc2) + f2hi(acc2);
        ps.w = f2lo(acc3) + f2hi(acc3);
        *(float4*)(partial + kq * 256 + u0) = ps;             // STS.128 conflict-free
        __syncthreads();

        if (tid < 256) {
            float s0 = partial[           tid] + partial[ 256 + tid];
            float s1 = partial[ 512 + tid] + partial[ 768 + tid];
            float s2 = partial[1024 + tid] + partial[1280 + tid];
            float s3 = partial[1536 + tid] + partial[1792 + tid];
            float y  = ((s0 + s1) + (s2 + s3)) + (hreg + breg);
            float x  = tanh_fast(y);
            sxf[tid] = x;                                     // new state
            outp[(size_t)t * (BB * UU)] = x;                  // overwrite h[t]
        }
        __syncthreads();
    }
}

// ---------------------------------------------------------------------------
// Launch. Inputs: inputs[B,T,F], R[F,U], W[U,U], bias[U], x0[U].
// Output: float32 states[T,B,U].
// ---------------------------------------------------------------------------
extern "C" void kernel_launch(void* const* d_in, const int* in_sizes, int n_in,
                              void* d_out, int out_size) {
    const float* inp  = (const float*)d_in[0];
    const float* R    = (const float*)d_in[1];
    const float* W    = (const float*)d_in[2];
    const float* bias = (const float*)d_in[3];
    const float* x0   = (const float*)d_in[4];
    float* out = (float*)d_out;

    cudaFuncSetAttribute(proj_kernel, cudaFuncAttributeMaxDynamicSharedMemorySize, PROJ_SMEM);
    cudaFuncSetAttribute(rec_kernel,  cudaFuncAttributeMaxDynamicSharedMemorySize, REC_SMEM);

    proj_kernel<<<dim3(TT / ROWS_PER_CTA, BB), 256, PROJ_SMEM>>>(inp, R, out);
    rec_kernel<<<BB, 512, REC_SMEM>>>(W, bias, x0, out);
}